// round 2
// baseline (speedup 1.0000x reference)
#include <cuda_runtime.h>
#include <cuda_bf16.h>

// GaussianSmoother: out[b,n] = sum_t x[b,t,n] * k[t]
// x: [B=64, T=2048, N=1024] fp32, k = Gaussian(sigma=20, center=T/2), normalized.
//
// Optimization: Gaussian support is effectively [center-W, center+W] with
// W=128 (6.4 sigma; truncated tail mass ~1e-10, far below the 1e-3 rel-err
// threshold). This cuts HBM traffic 8x (512 MiB -> 64.3 MiB).
// Normalization Z = sum_t exp(-0.5*((t-c)/sigma)^2) over the full 2048 taps
// equals sigma*sqrt(2*pi) to ~e^-7800 relative error (Poisson summation),
// so it's a compile-time constant.

#define B_DIM 64
#define T_DIM 2048
#define N_DIM 1024
#define CENTER 1024
#define W 128
#define TAPS (2 * W + 1)   // 257
#define SIGMA 20.0f

// 1 / (sigma * sqrt(2*pi)) for sigma = 20
#define INV_Z 0.019947114020071634f

__global__ __launch_bounds__(128) void gaussian_smooth_kernel(
    const float* __restrict__ x, float* __restrict__ out)
{
    __shared__ float k[TAPS];

    // Build normalized Gaussian weights for the window (once per block).
    for (int i = threadIdx.x; i < TAPS; i += blockDim.x) {
        float d = (float)(i - W) * (1.0f / SIGMA);
        k[i] = expf(-0.5f * d * d) * INV_Z;
    }
    __syncthreads();

    // One thread per output element (b, n). Consecutive threads hit
    // consecutive n -> fully coalesced 128B lines per warp per tap.
    int idx = blockIdx.x * blockDim.x + threadIdx.x;   // 0 .. B*N-1
    int b = idx >> 10;            // idx / N_DIM
    int n = idx & (N_DIM - 1);    // idx % N_DIM

    const float* p = x + (size_t)b * T_DIM * N_DIM
                       + (size_t)(CENTER - W) * N_DIM
                       + n;

    float acc = 0.0f;
    #pragma unroll 8
    for (int i = 0; i < TAPS; i++) {
        acc += p[(size_t)i * N_DIM] * k[i];
    }

    out[idx] = acc;
}

extern "C" void kernel_launch(void* const* d_in, const int* in_sizes, int n_in,
                              void* d_out, int out_size)
{
    const float* x = (const float*)d_in[0];
    float* out = (float*)d_out;

    const int total = B_DIM * N_DIM;      // 65536 outputs
    const int threads = 128;
    const int blocks = total / threads;   // 512

    gaussian_smooth_kernel<<<blocks, threads>>>(x, out);
}

// round 3
// speedup vs baseline: 1.5394x; 1.5394x over previous
#include <cuda_runtime.h>
#include <cuda_bf16.h>

// GaussianSmoother: out[b,n] = sum_t x[b,t,n] * k[t]
// x: [B=64, T=2048, N=1024] fp32.
//
// R1 insight: Gaussian support truncated to +/-128 taps (6.4 sigma,
// tail ~1e-10) -> 64.3 MiB traffic. Normalization Z = sigma*sqrt(2pi)
// (Poisson summation, error ~e^-7800) -> compile-time constant.
//
// R2 insight: was latency-bound (DRAM 32.7%, occ 20.6%). Split the
// 257-tap window across 4 thread-groups per output + smem reduction:
// 4x thread count (262144), ~64 loads/thread, unroll 16 for MLP.

#define B_DIM 64
#define T_DIM 2048
#define N_DIM 1024
#define CENTER 1024
#define W 128
#define TAPS (2 * W + 1)   // 257
#define SIGMA 20.0f

// 1 / (sigma * sqrt(2*pi)) for sigma = 20
#define INV_Z 0.019947114020071634f

#define BLOCK_THREADS 512
#define N_PER_BLOCK 128
#define GROUPS 4
#define TAPS_PER_GROUP 64   // groups 0..2: 64, group 3: 65

__global__ __launch_bounds__(BLOCK_THREADS) void gaussian_smooth_kernel(
    const float* __restrict__ x, float* __restrict__ out)
{
    __shared__ float k[TAPS];
    __shared__ float partial[GROUPS - 1][N_PER_BLOCK];

    int tid = threadIdx.x;

    // Build normalized Gaussian weights (once per block).
    for (int i = tid; i < TAPS; i += BLOCK_THREADS) {
        float d = (float)(i - W) * (1.0f / SIGMA);
        k[i] = expf(-0.5f * d * d) * INV_Z;
    }
    __syncthreads();

    int nl = tid & (N_PER_BLOCK - 1);   // output lane within block
    int g  = tid >> 7;                  // tap-group 0..3

    int idx = blockIdx.x * N_PER_BLOCK + nl;   // global output index
    int b = idx >> 10;            // idx / N_DIM
    int n = idx & (N_DIM - 1);    // idx % N_DIM

    int t0 = g * TAPS_PER_GROUP;

    const float* p = x + (size_t)b * T_DIM * N_DIM
                       + (size_t)(CENTER - W + t0) * N_DIM
                       + n;

    float acc = 0.0f;
    #pragma unroll 16
    for (int i = 0; i < TAPS_PER_GROUP; i++) {
        acc += p[(size_t)i * N_DIM] * k[t0 + i];
    }
    // group 3 takes the one leftover tap (257 = 4*64 + 1)
    if (g == GROUPS - 1) {
        acc += p[(size_t)TAPS_PER_GROUP * N_DIM] * k[TAPS - 1];
    }

    if (g > 0) {
        partial[g - 1][nl] = acc;
    }
    __syncthreads();

    if (g == 0) {
        acc += partial[0][nl] + partial[1][nl] + partial[2][nl];
        out[idx] = acc;
    }
}

extern "C" void kernel_launch(void* const* d_in, const int* in_sizes, int n_in,
                              void* d_out, int out_size)
{
    const float* x = (const float*)d_in[0];
    float* out = (float*)d_out;

    const int blocks = (B_DIM * N_DIM) / N_PER_BLOCK;   // 512

    gaussian_smooth_kernel<<<blocks, BLOCK_THREADS>>>(x, out);
}